// round 5
// baseline (speedup 1.0000x reference)
#include <cuda_runtime.h>
#include <cuda_bf16.h>
#include <cstdint>

// Dequant: out[r][c] = (float)q[r][c] * row_stats[r] * (1/127)
// ROWS = COLS = 8192, int32 in -> fp32 out. Pure streaming: 512 MiB total.
//
// R5: R3 layout (proven best): one block == one row, 256 thr x 8 int4,
// loads strided 4 KB apart, front-batched (MLP=8), uniform per-block scale.
// Change vs R3: loads keep .cs (zero reuse) but stores use DEFAULT policy —
// every 128 B line is fully overwritten, so normal L2 write-back lets the
// 126 MB L2 buffer the write stream and drain it in long bursts instead of
// .cs forcing early evictions interleaved with the read stream.

#define VPT 8                         // int4 vectors per thread
#define TPB 256                       // TPB*VPT = 2048 vecs = 8192 cols = 1 row

__global__ void __launch_bounds__(TPB, 6)
dequant_kernel(const int4* __restrict__ q,
               const float* __restrict__ row_stats,
               float4* __restrict__ out)
{
    // Uniform per-block scale: block r handles row r.
    const float scale = __ldg(&row_stats[blockIdx.x]) * (1.0f / 127.0f);

    const int base = blockIdx.x * (TPB * VPT) + threadIdx.x;

    // Front-batch 8 independent LDG.E.128 (MLP=8), streaming hint.
    int4 v[VPT];
#pragma unroll
    for (int j = 0; j < VPT; j++)
        v[j] = __ldcs(&q[base + j * TPB]);

#pragma unroll
    for (int j = 0; j < VPT; j++) {
        float4 r;
        r.x = (float)v[j].x * scale;
        r.y = (float)v[j].y * scale;
        r.z = (float)v[j].z * scale;
        r.w = (float)v[j].w * scale;
        out[base + j * TPB] = r;      // default STG: L2 write-back buffering
    }
}

extern "C" void kernel_launch(void* const* d_in, const int* in_sizes, int n_in,
                              void* d_out, int out_size)
{
    const int4*  q         = (const int4*)d_in[0];   // int32 [8192,8192]
    const float* row_stats = (const float*)d_in[1];  // fp32  [8192]
    float4*      out       = (float4*)d_out;

    const int rows = in_sizes[1];                    // 8192 blocks, one per row

    dequant_kernel<<<rows, TPB>>>(q, row_stats, out);
}

// round 6
// speedup vs baseline: 1.0086x; 1.0086x over previous
#include <cuda_runtime.h>
#include <cuda_bf16.h>
#include <cstdint>

// Dequant: out[r][c] = (float)q[r][c] * row_stats[r] * (1/127)
// ROWS = COLS = 8192, int32 in -> fp32 out. Pure streaming: 512 MiB total.
//
// FINAL (= R3, the measured-best config across the R2-R5 sweep):
//  - one block == one row: 256 threads x 8 int4 vecs = 2048 vecs = 8192 cols,
//    so the row scale is uniform per block (single __ldg, no per-vec ALU).
//  - 8 front-batched independent LDG.E.128 per thread (MLP=8).
//  - streaming .cs hints on BOTH loads and stores (zero reuse either way;
//    measured: .cs/.cs 73.9us > .cs/default 75.5us > contiguous-warp 75.2us).
// At 82% DRAM-active / 6.5 TB/s this sits on the B300 mixed read+write
// HBM-stream ceiling; traffic (512 MiB) is fixed by the I/O contract.

#define VPT 8                         // int4 vectors per thread
#define TPB 256                       // TPB*VPT = 2048 vecs = 8192 cols = 1 row

__global__ void __launch_bounds__(TPB, 6)
dequant_kernel(const int4* __restrict__ q,
               const float* __restrict__ row_stats,
               float4* __restrict__ out)
{
    // Uniform per-block scale: block r handles row r.
    const float scale = __ldg(&row_stats[blockIdx.x]) * (1.0f / 127.0f);

    const int base = blockIdx.x * (TPB * VPT) + threadIdx.x;

    // Front-batch 8 independent LDG.E.128 (MLP=8), streaming hint.
    int4 v[VPT];
#pragma unroll
    for (int j = 0; j < VPT; j++)
        v[j] = __ldcs(&q[base + j * TPB]);

#pragma unroll
    for (int j = 0; j < VPT; j++) {
        float4 r;
        r.x = (float)v[j].x * scale;
        r.y = (float)v[j].y * scale;
        r.z = (float)v[j].z * scale;
        r.w = (float)v[j].w * scale;
        __stcs(&out[base + j * TPB], r);   // streaming store (measured best)
    }
}

extern "C" void kernel_launch(void* const* d_in, const int* in_sizes, int n_in,
                              void* d_out, int out_size)
{
    const int4*  q         = (const int4*)d_in[0];   // int32 [8192,8192]
    const float* row_stats = (const float*)d_in[1];  // fp32  [8192]
    float4*      out       = (float4*)d_out;

    const int rows = in_sizes[1];                    // 8192 blocks, one per row

    dequant_kernel<<<rows, TPB>>>(q, row_stats, out);
}